// round 14
// baseline (speedup 1.0000x reference)
#include <cuda_runtime.h>
#include <cuda_bf16.h>
#include <cuda_fp16.h>
#include <math.h>
#include <stdint.h>

#define Bz   64
#define Tt   256
#define Vv   4096
#define Ee   512
#define Hh   1024
#define BT   (Bz*Tt)
#define CAT  (Ee+Hh)

// ---------------- static device scratch ----------------
__device__ float          g_pre[3u * BT * Hh];     // [gate][bt][n] gate 0=r,1=z,2=hbar
__device__ float          g_h[Bz * Hh];            // fp32 state [m][n]
__device__ float          g_zz[Bz * Hh];           // z [m][n]
__device__ __half         g_sh[Bz * Hh];           // fp16 state [m][k]
__device__ __half         g_rh[Bz * Hh];           // fp16 r*h [m][k]
__device__ unsigned       g_bar[1024];
__device__ __nv_bfloat16  g_ehi[BT * Ee];
__device__ __nv_bfloat16  g_elo[BT * Ee];
__device__ __nv_bfloat16  g_hhi[BT * Hh];          // hidden (head input) [bt][k]
__device__ __nv_bfloat16  g_hlo[BT * Hh];
__device__ __nv_bfloat16  g_wchi[3 * Hh * Ee];     // gate weights E-part [3072][512]
__device__ __nv_bfloat16  g_wclo[3 * Hh * Ee];
__device__ __half         g_wH[3u * Hh * Hh];      // gate weights H-part fp16 (single)
__device__ __nv_bfloat16  g_whhi[Vv * Hh];
__device__ __nv_bfloat16  g_whlo[Vv * Hh];

// ---------------- helpers ----------------
__device__ __forceinline__ uint32_t smem_u32(const void* p) {
    uint32_t a;
    asm("{ .reg .u64 t; cvta.to.shared.u64 t, %1; cvt.u32.u64 %0, t; }" : "=r"(a) : "l"(p));
    return a;
}
#define CP_COMMIT() asm volatile("cp.async.commit_group;" ::: "memory")
#define CP_WAIT(n)  asm volatile("cp.async.wait_group %0;" :: "n"(n) : "memory")
#define CPA(dst, src) \
    asm volatile("cp.async.cg.shared.global [%0], [%1], 16;" :: "r"(dst), "l"(src) : "memory")
#define SW128(x) ((x) ^ (((x) >> 3) & 0x70))

#define LDSM4(r, addr) \
    asm volatile("ldmatrix.sync.aligned.m8n8.x4.shared.b16 {%0,%1,%2,%3}, [%4];" \
        : "=r"((r)[0]), "=r"((r)[1]), "=r"((r)[2]), "=r"((r)[3]) : "r"(addr))

#define MMA(d, a, b) \
    asm volatile("mma.sync.aligned.m16n8k16.row.col.f32.bf16.bf16.f32 " \
        "{%0,%1,%2,%3}, {%4,%5,%6,%7}, {%8,%9}, {%0,%1,%2,%3};" \
        : "+f"((d)[0]), "+f"((d)[1]), "+f"((d)[2]), "+f"((d)[3]) \
        : "r"((a)[0]), "r"((a)[1]), "r"((a)[2]), "r"((a)[3]), "r"((b)[0]), "r"((b)[1]))

#define MMAH(d, a, b) \
    asm volatile("mma.sync.aligned.m16n8k16.row.col.f32.f16.f16.f32 " \
        "{%0,%1,%2,%3}, {%4,%5,%6,%7}, {%8,%9}, {%0,%1,%2,%3};" \
        : "+f"((d)[0]), "+f"((d)[1]), "+f"((d)[2]), "+f"((d)[3]) \
        : "r"((a)[0]), "r"((a)[1]), "r"((a)[2]), "r"((a)[3]), "r"((b)[0]), "r"((b)[1]))

__device__ __forceinline__ void split2(float a, float b, __nv_bfloat162* hi, __nv_bfloat162* lo) {
    __nv_bfloat16 ah = __float2bfloat16(a), bh = __float2bfloat16(b);
    *hi = __nv_bfloat162(ah, bh);
    *lo = __nv_bfloat162(__float2bfloat16(a - __bfloat162float(ah)),
                         __float2bfloat16(b - __bfloat162float(bh)));
}

// ---------------- init / embed / converters ----------------
__global__ void k_init(const float* __restrict__ start) {
    int i = blockIdx.x * blockDim.x + threadIdx.x;   // 65536
    float v = start[i & 1023];
    g_h[i] = v;
    g_sh[i] = __float2half_rn(v);
    if (i < 1024) g_bar[i] = 0u;
}
__global__ void k_embed(const int* __restrict__ x, const float* __restrict__ wte) {
    int i  = blockIdx.x * blockDim.x + threadIdx.x;
    int bt = i >> 7, e4 = i & 127;
    int tok = x[bt];
    float4 v = reinterpret_cast<const float4*>(wte + (size_t)tok * Ee)[e4];
    __nv_bfloat162 h0, l0, h1, l1;
    split2(v.x, v.y, &h0, &l0); split2(v.z, v.w, &h1, &l1);
    reinterpret_cast<__nv_bfloat162*>(g_ehi)[2*i]   = h0;
    reinterpret_cast<__nv_bfloat162*>(g_ehi)[2*i+1] = h1;
    reinterpret_cast<__nv_bfloat162*>(g_elo)[2*i]   = l0;
    reinterpret_cast<__nv_bfloat162*>(g_elo)[2*i+1] = l1;
}
__global__ void k_cvt(const float* __restrict__ src, __nv_bfloat16* __restrict__ hi,
                      __nv_bfloat16* __restrict__ lo) {
    int i = blockIdx.x * blockDim.x + threadIdx.x;
    float4 v = reinterpret_cast<const float4*>(src)[i];
    __nv_bfloat162 h0, l0, h1, l1;
    split2(v.x, v.y, &h0, &l0); split2(v.z, v.w, &h1, &l1);
    reinterpret_cast<__nv_bfloat162*>(hi)[2*i]   = h0;
    reinterpret_cast<__nv_bfloat162*>(hi)[2*i+1] = h1;
    reinterpret_cast<__nv_bfloat162*>(lo)[2*i]   = l0;
    reinterpret_cast<__nv_bfloat162*>(lo)[2*i+1] = l1;
}
__global__ void k_cvt_wcat(const float* __restrict__ Wr, const float* __restrict__ Wz,
                           const float* __restrict__ Wbar) {
    int i = blockIdx.x * blockDim.x + threadIdx.x;    // 3072*512
    int row = i >> 9, col = i & 511;
    const float* W = (row < 1024) ? Wr : (row < 2048) ? Wz : Wbar;
    float v = W[(size_t)(row & 1023) * CAT + col];
    __nv_bfloat16 h = __float2bfloat16(v);
    g_wchi[i] = h;
    g_wclo[i] = __float2bfloat16(v - __bfloat162float(h));
}
__global__ void k_cvt_wH(const float* __restrict__ Wr, const float* __restrict__ Wz,
                         const float* __restrict__ Wbar) {
    int i = blockIdx.x * blockDim.x + threadIdx.x;    // 3*1024*1024
    int gate = i >> 20, row = (i >> 10) & 1023, col = i & 1023;
    const float* W = (gate == 0) ? Wr : (gate == 1) ? Wz : Wbar;
    g_wH[i] = __float2half_rn(W[(size_t)row * CAT + Ee + col]);
}

// ---------------- split-bf16 HMMA GEMM (pre-projections + head, unchanged) ----------------
#define STG      65536
#define SOFF_ALO 16384
#define SOFF_BHI 32768
#define SOFF_BLO 49152
#define SM_TOTAL 131072

__device__ __forceinline__ void load_chunk(
    uint32_t sb, int s, int tid,
    const __nv_bfloat16* Ahi, const __nv_bfloat16* Alo,
    const __nv_bfloat16* Bhi, const __nv_bfloat16* Blo,
    int m0, int n0, int kc, int K)
{
    uint32_t st = sb + s * STG;
    int kb = kc * 64;
    #pragma unroll
    for (int j = 0; j < 4; j++) {
        int q = tid + j * 256, row = q >> 3, kg = q & 7;
        uint32_t d = SW128((uint32_t)(row * 128 + kg * 16));
        size_t srcA = (size_t)(m0 + row) * K + kb + kg * 8;
        size_t srcB = (size_t)(n0 + row) * K + kb + kg * 8;
        CPA(st + d,            Ahi + srcA);
        CPA(st + SOFF_ALO + d, Alo + srcA);
        CPA(st + SOFF_BHI + d, Bhi + srcB);
        CPA(st + SOFF_BLO + d, Blo + srcB);
    }
}

__global__ void __launch_bounds__(256, 1) k_tgemm(
    const __nv_bfloat16* __restrict__ Ahi, const __nv_bfloat16* __restrict__ Alo,
    const __nv_bfloat16* __restrict__ Bhi, const __nv_bfloat16* __restrict__ Blo,
    const float* __restrict__ bias, float* __restrict__ C, int K, int ldc, int nk)
{
    extern __shared__ char smem[];
    const uint32_t sb = smem_u32(smem);
    const int tid = threadIdx.x, lane = tid & 31, wid = tid >> 5;
    const int wm = wid & 3, wn = wid >> 2;
    const int m0 = blockIdx.y * 128, n0 = blockIdx.x * 128;

    float acc[2][8][4] = {};

    load_chunk(sb, 0, tid, Ahi, Alo, Bhi, Blo, m0, n0, 0, K);
    CP_COMMIT();

    for (int kc = 0; kc < nk; kc++) {
        if (kc + 1 < nk) {
            load_chunk(sb, (kc + 1) & 1, tid, Ahi, Alo, Bhi, Blo, m0, n0, kc + 1, K);
            CP_COMMIT();
            CP_WAIT(1);
        } else {
            CP_WAIT(0);
        }
        __syncthreads();

        const uint32_t st = sb + (kc & 1) * STG;
        #pragma unroll
        for (int ks = 0; ks < 4; ks++) {
            uint32_t a_hi[2][4], a_lo[2][4];
            {
                int acol = ks * 32 + (lane >> 4) * 16;
                #pragma unroll
                for (int mt = 0; mt < 2; mt++) {
                    int arow = wm * 32 + mt * 16 + (lane & 15);
                    uint32_t off = SW128((uint32_t)(arow * 128 + acol));
                    LDSM4(a_hi[mt], st + off);
                    LDSM4(a_lo[mt], st + SOFF_ALO + off);
                }
            }
            uint32_t b_hi[8][2], b_lo[8][2];
            {
                int bcol  = ks * 32 + ((lane >> 3) & 1) * 16;
                int brofs = (lane >> 4) * 8 + (lane & 7);
                #pragma unroll
                for (int nt2 = 0; nt2 < 4; nt2++) {
                    int brow = wn * 64 + nt2 * 16 + brofs;
                    uint32_t off = SW128((uint32_t)(brow * 128 + bcol));
                    uint32_t r[4];
                    LDSM4(r, st + SOFF_BHI + off);
                    b_hi[nt2*2][0]   = r[0]; b_hi[nt2*2][1]   = r[1];
                    b_hi[nt2*2+1][0] = r[2]; b_hi[nt2*2+1][1] = r[3];
                    LDSM4(r, st + SOFF_BLO + off);
                    b_lo[nt2*2][0]   = r[0]; b_lo[nt2*2][1]   = r[1];
                    b_lo[nt2*2+1][0] = r[2]; b_lo[nt2*2+1][1] = r[3];
                }
            }
            #pragma unroll
            for (int mt = 0; mt < 2; mt++)
                #pragma unroll
                for (int nt = 0; nt < 8; nt++) {
                    MMA(acc[mt][nt], a_hi[mt], b_hi[nt]);
                    MMA(acc[mt][nt], a_hi[mt], b_lo[nt]);
                    MMA(acc[mt][nt], a_lo[mt], b_hi[nt]);
                }
        }
        __syncthreads();
    }

    const int g = lane >> 2, tg = lane & 3;
    #pragma unroll
    for (int nt = 0; nt < 8; nt++) {
        int col = n0 + wn * 64 + nt * 8 + tg * 2;
        float b0 = bias[col], b1 = bias[col + 1];
        #pragma unroll
        for (int mt = 0; mt < 2; mt++) {
            int r0 = m0 + wm * 32 + mt * 16 + g;
            float2 v0 = make_float2(acc[mt][nt][0] + b0, acc[mt][nt][1] + b1);
            float2 v1 = make_float2(acc[mt][nt][2] + b0, acc[mt][nt][3] + b1);
            *reinterpret_cast<float2*>(C + (size_t)r0 * ldc + col)       = v0;
            *reinterpret_cast<float2*>(C + (size_t)(r0 + 8) * ldc + col) = v1;
        }
    }
}

// ---------------- grid barrier (release-arrive / acquire-poll) ----------------
__device__ __forceinline__ void gbarrier(int idx, unsigned G) {
    __syncthreads();
    if (threadIdx.x == 0) {
        unsigned a;
        asm volatile("atom.release.gpu.global.add.u32 %0, [%1], 1;"
                     : "=r"(a) : "l"(g_bar + idx) : "memory");
        if (a + 1u < G) {
            unsigned v;
            do {
                asm volatile("ld.acquire.gpu.global.u32 %0, [%1];"
                             : "=r"(v) : "l"(g_bar + idx) : "memory");
            } while (v < G);
        }
    }
    __syncthreads();
}

// ---------------- fp16 HMMA persistent scan (m-split both phases, full staging) ----------------
// 128 blocks x 256 threads. smem: WS1 64K (32 cols) | WS2 32K (16 cols) | STAGE 64K (RED aliased)
#define SC_WS1   0
#define SC_WS2   65536
#define SC_STAGE 98304
#define SC_TOTAL 163840

// staging: 32 rows (m-half mh) x k128 chunk c -> STAGE + c*8K (no reuse)
__device__ __forceinline__ void stageS(uint32_t sb, int c, int tid, int mh, const __half* s)
{
    uint32_t base = sb + SC_STAGE + (uint32_t)c * 8192;
    #pragma unroll
    for (int j = 0; j < 2; j++) {
        int q = tid + j * 256;               // < 512
        int sub = q >> 8, m = (q >> 3) & 31, kg = q & 7;
        uint32_t d = sub * 4096 + SW128((uint32_t)(m * 128 + kg * 16));
        size_t src = (size_t)(mh * 32 + m) * 1024 + c * 128 + sub * 64 + kg * 8;
        CPA(base + d, s + src);
    }
}

// phase1 mma: 32 cols (4 n8 tiles), warp = mt2 (m16) x kq (k32 of k128 chunk)
__device__ __forceinline__ void mma_chunk1(uint32_t sb, int c, int lane, int mt2, int kq,
                                           float acc[4][4])
{
    uint32_t sh = sb + SC_STAGE + (uint32_t)c * 8192 + (kq >> 1) * 4096;
    uint32_t wh = sb + SC_WS1 + (uint32_t)(c * 2 + (kq >> 1)) * 4096;
    uint32_t aoff0 = (uint32_t)((mt2 * 16 + (lane & 15)) * 128 + (lane >> 4) * 16 + (kq & 1) * 64);
    uint32_t boff0 = (uint32_t)((((lane >> 4) << 3) + (lane & 7)) * 128
                              + ((lane >> 3) & 1) * 16 + (kq & 1) * 64);
    #pragma unroll
    for (int ks = 0; ks < 2; ks++) {
        uint32_t offA = SW128(aoff0 + ks * 32);
        uint32_t a[4];
        LDSM4(a, sh + offA);
        #pragma unroll
        for (int nt2 = 0; nt2 < 2; nt2++) {
            uint32_t offB = SW128(boff0 + nt2 * 16 * 128 + ks * 32);
            uint32_t bh[4];
            LDSM4(bh, wh + offB);
            MMAH(acc[nt2*2],     a, bh);
            MMAH(acc[nt2*2 + 1], a, bh + 2);
        }
    }
}

// phase2 mma: 16 cols (2 n8 tiles)
__device__ __forceinline__ void mma_chunk2(uint32_t sb, int c, int lane, int mt2, int kq,
                                           float acc[2][4])
{
    uint32_t sh = sb + SC_STAGE + (uint32_t)c * 8192 + (kq >> 1) * 4096;
    uint32_t wh = sb + SC_WS2 + (uint32_t)(c * 2 + (kq >> 1)) * 2048;
    uint32_t aoff0 = (uint32_t)((mt2 * 16 + (lane & 15)) * 128 + (lane >> 4) * 16 + (kq & 1) * 64);
    uint32_t boff0 = (uint32_t)((((lane >> 4) << 3) + (lane & 7)) * 128
                              + ((lane >> 3) & 1) * 16 + (kq & 1) * 64);
    #pragma unroll
    for (int ks = 0; ks < 2; ks++) {
        uint32_t offA = SW128(aoff0 + ks * 32);
        uint32_t offB = SW128(boff0 + ks * 32);
        uint32_t a[4], bh[4];
        LDSM4(a, sh + offA);
        LDSM4(bh, wh + offB);
        MMAH(acc[0], a, bh);
        MMAH(acc[1], a, bh + 2);
    }
}

#define P1STEP(c, wcnt) do { \
    CP_WAIT(wcnt); __syncthreads(); \
    mma_chunk1(sb, (c), lane, mt2, kq, acc); \
} while (0)

#define P2STEP(c, wcnt) do { \
    CP_WAIT(wcnt); __syncthreads(); \
    mma_chunk2(sb, (c), lane, mt2, kq, acc2); \
} while (0)

__global__ void __launch_bounds__(256, 1) k_scan() {
    extern __shared__ char sm[];
    const uint32_t sb = smem_u32(sm);
    float* redf = reinterpret_cast<float*>(sm + SC_STAGE);   // aliased over consumed stage
    const int tid = threadIdx.x, lane = tid & 31, w = tid >> 5;
    const int g = blockIdx.x;
    const unsigned G = gridDim.x;
    // phase1: gate = g>>6 (0=r,1=z), mh1 = (g>>5)&1, 32 cols
    const int gate = g >> 6;
    const int mh1  = (g >> 5) & 1;
    const int n0p1 = (g & 31) * 32;
    // phase2: mh2 = g>>6, 16 cols
    const int mh2  = g >> 6;
    const int n0p2 = (g & 63) * 16;
    const int mt2 = w & 1, kq = w >> 1;      // both phases: 2 m-tiles x 4 k32-quarters
    const int gg = lane >> 2, tg = lane & 3;

    // ---- resident weights (single fp16) ----
    {   // WS1: 32 cols, chunked [sc16][r32][k64] (4KB sub-chunks)
        const __half* W1 = g_wH + (size_t)gate * (Hh * Hh) + (size_t)n0p1 * 1024;
        #pragma unroll
        for (int j = 0; j < 16; j++) {
            int q = tid + j * 256;           // < 4096
            int sc = q >> 8, r = (q >> 3) & 31, kg = q & 7;
            uint32_t d = sc * 4096 + SW128((uint32_t)(r * 128 + kg * 16));
            size_t src = (size_t)r * 1024 + sc * 64 + kg * 8;
            CPA(sb + SC_WS1 + d, W1 + src);
        }
    }
    {   // WS2: 16 cols, chunked [sc16][r16][k64] (2KB sub-chunks)
        const __half* W2 = g_wH + 2u * (Hh * Hh) + (size_t)n0p2 * 1024;
        #pragma unroll
        for (int j = 0; j < 8; j++) {
            int q = tid + j * 256;           // < 2048
            int sc = q >> 7, r = (q >> 3) & 15, kg = q & 7;
            uint32_t d = sc * 2048 + SW128((uint32_t)(r * 128 + kg * 16));
            size_t src = (size_t)r * 1024 + sc * 64 + kg * 8;
            CPA(sb + SC_WS2 + d, W2 + src);
        }
    }
    CP_COMMIT();
    CP_WAIT(0);
    __syncthreads();

    const float* pre1 = g_pre + (size_t)gate * BT * Hh;
    const float* pre2 = g_pre + 2 * (size_t)BT * Hh;

    for (int t = 0; t < Tt; t++) {
        // ---- prefetch phase1 epilogue operands (warps 0-1) ----
        float2 pv[4][2], hv[4][2];
        if (w < 2) {
            #pragma unroll
            for (int nt = 0; nt < 4; nt++)
                #pragma unroll
                for (int rr = 0; rr < 2; rr++) {
                    int m = mh1 * 32 + mt2 * 16 + gg + rr * 8;
                    int n = n0p1 + nt * 8 + tg * 2;
                    pv[nt][rr] = *reinterpret_cast<const float2*>(&pre1[(size_t)(m * Tt + t) * Hh + n]);
                    if (gate == 0) hv[nt][rr] = *reinterpret_cast<const float2*>(&g_h[m * 1024 + n]);
                }
        }

        // ======== phase 1: r / z, 32 rows x 32 cols, 8 k128 chunks ========
        float acc[4][4] = {};
        #pragma unroll
        for (int c = 0; c < 8; c++) { stageS(sb, c, tid, mh1, g_sh); CP_COMMIT(); }
        P1STEP(0, 7); P1STEP(1, 6); P1STEP(2, 5); P1STEP(3, 4);
        P1STEP(4, 3); P1STEP(5, 2); P1STEP(6, 1); P1STEP(7, 0);
        __syncthreads();                      // chunk reads done before red (aliased) write
        if (kq > 0) {
            int slot = (kq - 1) * 2 + mt2;
            #pragma unroll
            for (int nt = 0; nt < 4; nt++)
                #pragma unroll
                for (int i = 0; i < 4; i++)
                    redf[slot * 512 + lane * 16 + nt * 4 + i] = acc[nt][i];
        }
        __syncthreads();
        // prefetch phase2 operands independent of phase1 output
        float2 pv2[2][2], hpv[2][2];
        if (w < 2) {
            #pragma unroll
            for (int nt = 0; nt < 2; nt++)
                #pragma unroll
                for (int rr = 0; rr < 2; rr++) {
                    int m = mh2 * 32 + mt2 * 16 + gg + rr * 8;
                    int n = n0p2 + nt * 8 + tg * 2;
                    pv2[nt][rr] = *reinterpret_cast<const float2*>(&pre2[(size_t)(m * Tt + t) * Hh + n]);
                    hpv[nt][rr] = *reinterpret_cast<const float2*>(&g_h[m * 1024 + n]);
                }
        }
        if (w < 2) {
            #pragma unroll
            for (int q2 = 0; q2 < 3; q2++)
                #pragma unroll
                for (int nt = 0; nt < 4; nt++)
                    #pragma unroll
                    for (int i = 0; i < 4; i++)
                        acc[nt][i] += redf[(q2 * 2 + mt2) * 512 + lane * 16 + nt * 4 + i];
            #pragma unroll
            for (int nt = 0; nt < 4; nt++) {
                #pragma unroll
                for (int rr = 0; rr < 2; rr++) {
                    int m = mh1 * 32 + mt2 * 16 + gg + rr * 8;
                    int n = n0p1 + nt * 8 + tg * 2;
                    float v0 = acc[nt][rr * 2 + 0] + pv[nt][rr].x;
                    float v1 = acc[nt][rr * 2 + 1] + pv[nt][rr].y;
                    float s0 = 1.f / (1.f + __expf(-v0));
                    float s1 = 1.f / (1.f + __expf(-v1));
                    if (gate == 0) {
                        float rh0 = s0 * hv[nt][rr].x, rh1 = s1 * hv[nt][rr].y;
                        *reinterpret_cast<__half2*>(&g_rh[m * 1024 + n]) =
                            __floats2half2_rn(rh0, rh1);
                    } else {
                        *reinterpret_cast<float2*>(&g_zz[m * 1024 + n]) = make_float2(s0, s1);
                    }
                }
            }
        }
        gbarrier(2 * t, G);

        // ======== phase 2: hbar + update, 32 rows x 16 cols, 8 k128 chunks ========
        {
            float2 zv[2][2];
            if (w < 2) {
                #pragma unroll
                for (int nt = 0; nt < 2; nt++)
                    #pragma unroll
                    for (int rr = 0; rr < 2; rr++) {
                        int m = mh2 * 32 + mt2 * 16 + gg + rr * 8;
                        int n = n0p2 + nt * 8 + tg * 2;
                        zv[nt][rr] = *reinterpret_cast<const float2*>(&g_zz[m * 1024 + n]);
                    }
            }
            float acc2[2][4] = {};
            #pragma unroll
            for (int c = 0; c < 8; c++) { stageS(sb, c, tid, mh2, g_rh); CP_COMMIT(); }
            P2STEP(0, 7); P2STEP(1, 6); P2STEP(2, 5); P2STEP(3, 4);
            P2STEP(4, 3); P2STEP(5, 2); P2STEP(6, 1); P2STEP(7, 0);
            __syncthreads();
            if (kq > 0) {
                int slot = (kq - 1) * 2 + mt2;
                #pragma unroll
                for (int nt = 0; nt < 2; nt++)
                    #pragma unroll
                    for (int i = 0; i < 4; i++)
                        redf[slot * 256 + lane * 8 + nt * 4 + i] = acc2[nt][i];
            }
            __syncthreads();
            if (w < 2) {
                #pragma unroll
                for (int q2 = 0; q2 < 3; q2++)
                    #pragma unroll
                    for (int nt = 0; nt < 2; nt++)
                        #pragma unroll
                        for (int i = 0; i < 4; i++)
                            acc2[nt][i] += redf[(q2 * 2 + mt2) * 256 + lane * 8 + nt * 4 + i];
                #pragma unroll
                for (int nt = 0; nt < 2; nt++) {
                    #pragma unroll
                    for (int rr = 0; rr < 2; rr++) {
                        int m = mh2 * 32 + mt2 * 16 + gg + rr * 8;
                        int n = n0p2 + nt * 8 + tg * 2;
                        float hb0 = tanhf(acc2[nt][rr * 2 + 0] + pv2[nt][rr].x);
                        float hb1 = tanhf(acc2[nt][rr * 2 + 1] + pv2[nt][rr].y);
                        float hn0 = fmaf(zv[nt][rr].x, hb0 - hpv[nt][rr].x, hpv[nt][rr].x);
                        float hn1 = fmaf(zv[nt][rr].y, hb1 - hpv[nt][rr].y, hpv[nt][rr].y);
                        *reinterpret_cast<float2*>(&g_h[m * 1024 + n]) = make_float2(hn0, hn1);
                        *reinterpret_cast<__half2*>(&g_sh[m * 1024 + n]) =
                            __floats2half2_rn(hn0, hn1);
                        __nv_bfloat162 hi2, lo2;
                        split2(hn0, hn1, &hi2, &lo2);
                        size_t ho = (size_t)(m * Tt + t) * Hh + n;
                        *reinterpret_cast<__nv_bfloat162*>(&g_hhi[ho]) = hi2;
                        *reinterpret_cast<__nv_bfloat162*>(&g_hlo[ho]) = lo2;
                    }
                }
            }
        }
        gbarrier(2 * t + 1, G);
    }
}

// ---------------- launch ----------------
extern "C" void kernel_launch(void* const* d_in, const int* in_sizes, int n_in,
                              void* d_out, int out_size)
{
    const int*   x     = (const int*)  d_in[0];
    const float* start = (const float*)d_in[1];
    const float* wte   = (const float*)d_in[2];
    const float* Wr    = (const float*)d_in[3];
    const float* br    = (const float*)d_in[4];
    const float* Wbar  = (const float*)d_in[5];
    const float* bbar  = (const float*)d_in[6];
    const float* Wz    = (const float*)d_in[7];
    const float* bz    = (const float*)d_in[8];
    const float* Whead = (const float*)d_in[9];
    const float* bhead = (const float*)d_in[10];
    float* out = (float*)d_out;

    float* p_pre;
    __nv_bfloat16 *p_ehi, *p_elo, *p_hhi, *p_hlo, *p_wchi, *p_wclo, *p_whhi, *p_whlo;
    cudaGetSymbolAddress((void**)&p_pre,  g_pre);
    cudaGetSymbolAddress((void**)&p_ehi,  g_ehi);   cudaGetSymbolAddress((void**)&p_elo,  g_elo);
    cudaGetSymbolAddress((void**)&p_hhi,  g_hhi);   cudaGetSymbolAddress((void**)&p_hlo,  g_hlo);
    cudaGetSymbolAddress((void**)&p_wchi, g_wchi);  cudaGetSymbolAddress((void**)&p_wclo, g_wclo);
    cudaGetSymbolAddress((void**)&p_whhi, g_whhi);  cudaGetSymbolAddress((void**)&p_whlo, g_whlo);

    cudaFuncSetAttribute(k_scan,  cudaFuncAttributeMaxDynamicSharedMemorySize, SC_TOTAL);
    cudaFuncSetAttribute(k_tgemm, cudaFuncAttributeMaxDynamicSharedMemorySize, SM_TOTAL);

    k_init<<<256, 256>>>(start);
    k_embed<<<(BT * Ee / 4) / 256, 256>>>(x, wte);
    k_cvt_wcat<<<(3 * Hh * Ee) / 256, 256>>>(Wr, Wz, Wbar);
    k_cvt_wH<<<(3 * Hh * Hh) / 256, 256>>>(Wr, Wz, Wbar);
    k_cvt<<<(Vv * Hh / 4) / 256, 256>>>(Whead, p_whhi, p_whlo);

    // pre-projections: 3 gates, N=1024 each, K=512
    for (int gate = 0; gate < 3; gate++) {
        const float* bias = (gate == 0) ? br : (gate == 1) ? bz : bbar;
        k_tgemm<<<dim3(Hh/128, BT/128), 256, SM_TOTAL>>>(
            p_ehi, p_elo,
            p_wchi + (size_t)gate * Hh * Ee, p_wclo + (size_t)gate * Hh * Ee,
            bias, p_pre + (size_t)gate * BT * Hh, Ee, Hh, Ee/64);
    }

    k_scan<<<128, 256, SC_TOTAL>>>();

    k_tgemm<<<dim3(Vv/128, BT/128), 256, SM_TOTAL>>>(
        p_hhi, p_hlo, p_whhi, p_whlo, bhead, out, Hh, Vv, Hh/64);
}

// round 16
// speedup vs baseline: 1.0354x; 1.0354x over previous
#include <cuda_runtime.h>
#include <cuda_bf16.h>
#include <cuda_fp16.h>
#include <math.h>
#include <stdint.h>

#define Bz   64
#define Tt   256
#define Vv   4096
#define Ee   512
#define Hh   1024
#define BT   (Bz*Tt)
#define CAT  (Ee+Hh)

// ---------------- static device scratch ----------------
__device__ float          g_pre[3u * BT * Hh];     // [gate][bt][n] gate 0=r,1=z,2=hbar
__device__ float          g_h[Bz * Hh];            // fp32 state [m][n]
__device__ float          g_zz[Bz * Hh];           // z [m][n]
__device__ __half         g_sh[Bz * Hh];           // fp16 state [m][k]
__device__ __half         g_rh[Bz * Hh];           // fp16 r*h [m][k]
__device__ unsigned       g_bar[1024];
__device__ __nv_bfloat16  g_ehi[BT * Ee];
__device__ __nv_bfloat16  g_elo[BT * Ee];
__device__ __nv_bfloat16  g_hhi[BT * Hh];          // hidden (head input) [bt][k]
__device__ __nv_bfloat16  g_hlo[BT * Hh];
__device__ __nv_bfloat16  g_wchi[3 * Hh * Ee];     // gate weights E-part [3072][512]
__device__ __nv_bfloat16  g_wclo[3 * Hh * Ee];
__device__ __half         g_wH[3u * Hh * Hh];      // gate weights H-part fp16 (single)
__device__ __nv_bfloat16  g_whhi[Vv * Hh];
__device__ __nv_bfloat16  g_whlo[Vv * Hh];

// ---------------- helpers ----------------
__device__ __forceinline__ uint32_t smem_u32(const void* p) {
    uint32_t a;
    asm("{ .reg .u64 t; cvta.to.shared.u64 t, %1; cvt.u32.u64 %0, t; }" : "=r"(a) : "l"(p));
    return a;
}
#define CP_COMMIT() asm volatile("cp.async.commit_group;" ::: "memory")
#define CP_WAIT(n)  asm volatile("cp.async.wait_group %0;" :: "n"(n) : "memory")
#define CPA(dst, src) \
    asm volatile("cp.async.cg.shared.global [%0], [%1], 16;" :: "r"(dst), "l"(src) : "memory")
#define SW128(x) ((x) ^ (((x) >> 3) & 0x70))

#define LDSM4(r, addr) \
    asm volatile("ldmatrix.sync.aligned.m8n8.x4.shared.b16 {%0,%1,%2,%3}, [%4];" \
        : "=r"((r)[0]), "=r"((r)[1]), "=r"((r)[2]), "=r"((r)[3]) : "r"(addr))

#define MMA(d, a, b) \
    asm volatile("mma.sync.aligned.m16n8k16.row.col.f32.bf16.bf16.f32 " \
        "{%0,%1,%2,%3}, {%4,%5,%6,%7}, {%8,%9}, {%0,%1,%2,%3};" \
        : "+f"((d)[0]), "+f"((d)[1]), "+f"((d)[2]), "+f"((d)[3]) \
        : "r"((a)[0]), "r"((a)[1]), "r"((a)[2]), "r"((a)[3]), "r"((b)[0]), "r"((b)[1]))

#define MMAH(d, a, b) \
    asm volatile("mma.sync.aligned.m16n8k16.row.col.f32.f16.f16.f32 " \
        "{%0,%1,%2,%3}, {%4,%5,%6,%7}, {%8,%9}, {%0,%1,%2,%3};" \
        : "+f"((d)[0]), "+f"((d)[1]), "+f"((d)[2]), "+f"((d)[3]) \
        : "r"((a)[0]), "r"((a)[1]), "r"((a)[2]), "r"((a)[3]), "r"((b)[0]), "r"((b)[1]))

__device__ __forceinline__ void split2(float a, float b, __nv_bfloat162* hi, __nv_bfloat162* lo) {
    __nv_bfloat16 ah = __float2bfloat16(a), bh = __float2bfloat16(b);
    *hi = __nv_bfloat162(ah, bh);
    *lo = __nv_bfloat162(__float2bfloat16(a - __bfloat162float(ah)),
                         __float2bfloat16(b - __bfloat162float(bh)));
}

// ---------------- init / embed / converters ----------------
__global__ void k_init(const float* __restrict__ start) {
    int i = blockIdx.x * blockDim.x + threadIdx.x;   // 65536
    float v = start[i & 1023];
    g_h[i] = v;
    g_sh[i] = __float2half_rn(v);
    if (i < 1024) g_bar[i] = 0u;
}
__global__ void k_embed(const int* __restrict__ x, const float* __restrict__ wte) {
    int i  = blockIdx.x * blockDim.x + threadIdx.x;
    int bt = i >> 7, e4 = i & 127;
    int tok = x[bt];
    float4 v = reinterpret_cast<const float4*>(wte + (size_t)tok * Ee)[e4];
    __nv_bfloat162 h0, l0, h1, l1;
    split2(v.x, v.y, &h0, &l0); split2(v.z, v.w, &h1, &l1);
    reinterpret_cast<__nv_bfloat162*>(g_ehi)[2*i]   = h0;
    reinterpret_cast<__nv_bfloat162*>(g_ehi)[2*i+1] = h1;
    reinterpret_cast<__nv_bfloat162*>(g_elo)[2*i]   = l0;
    reinterpret_cast<__nv_bfloat162*>(g_elo)[2*i+1] = l1;
}
__global__ void k_cvt(const float* __restrict__ src, __nv_bfloat16* __restrict__ hi,
                      __nv_bfloat16* __restrict__ lo) {
    int i = blockIdx.x * blockDim.x + threadIdx.x;
    float4 v = reinterpret_cast<const float4*>(src)[i];
    __nv_bfloat162 h0, l0, h1, l1;
    split2(v.x, v.y, &h0, &l0); split2(v.z, v.w, &h1, &l1);
    reinterpret_cast<__nv_bfloat162*>(hi)[2*i]   = h0;
    reinterpret_cast<__nv_bfloat162*>(hi)[2*i+1] = h1;
    reinterpret_cast<__nv_bfloat162*>(lo)[2*i]   = l0;
    reinterpret_cast<__nv_bfloat162*>(lo)[2*i+1] = l1;
}
__global__ void k_cvt_wcat(const float* __restrict__ Wr, const float* __restrict__ Wz,
                           const float* __restrict__ Wbar) {
    int i = blockIdx.x * blockDim.x + threadIdx.x;    // 3072*512
    int row = i >> 9, col = i & 511;
    const float* W = (row < 1024) ? Wr : (row < 2048) ? Wz : Wbar;
    float v = W[(size_t)(row & 1023) * CAT + col];
    __nv_bfloat16 h = __float2bfloat16(v);
    g_wchi[i] = h;
    g_wclo[i] = __float2bfloat16(v - __bfloat162float(h));
}
__global__ void k_cvt_wH(const float* __restrict__ Wr, const float* __restrict__ Wz,
                         const float* __restrict__ Wbar) {
    int i = blockIdx.x * blockDim.x + threadIdx.x;    // 3*1024*1024
    int gate = i >> 20, row = (i >> 10) & 1023, col = i & 1023;
    const float* W = (gate == 0) ? Wr : (gate == 1) ? Wz : Wbar;
    g_wH[i] = __float2half_rn(W[(size_t)row * CAT + Ee + col]);
}

// ---------------- split-bf16 HMMA GEMM (pre-projections + head) ----------------
#define STG      65536
#define SOFF_ALO 16384
#define SOFF_BHI 32768
#define SOFF_BLO 49152
#define SM_TOTAL 131072

__device__ __forceinline__ void load_chunk(
    uint32_t sb, int s, int tid,
    const __nv_bfloat16* Ahi, const __nv_bfloat16* Alo,
    const __nv_bfloat16* Bhi, const __nv_bfloat16* Blo,
    int m0, int n0, int kc, int K)
{
    uint32_t st = sb + s * STG;
    int kb = kc * 64;
    #pragma unroll
    for (int j = 0; j < 4; j++) {
        int q = tid + j * 256, row = q >> 3, kg = q & 7;
        uint32_t d = SW128((uint32_t)(row * 128 + kg * 16));
        size_t srcA = (size_t)(m0 + row) * K + kb + kg * 8;
        size_t srcB = (size_t)(n0 + row) * K + kb + kg * 8;
        CPA(st + d,            Ahi + srcA);
        CPA(st + SOFF_ALO + d, Alo + srcA);
        CPA(st + SOFF_BHI + d, Bhi + srcB);
        CPA(st + SOFF_BLO + d, Blo + srcB);
    }
}

__global__ void __launch_bounds__(256, 1) k_tgemm(
    const __nv_bfloat16* __restrict__ Ahi, const __nv_bfloat16* __restrict__ Alo,
    const __nv_bfloat16* __restrict__ Bhi, const __nv_bfloat16* __restrict__ Blo,
    const float* __restrict__ bias, float* __restrict__ C, int K, int ldc, int nk)
{
    extern __shared__ char smem[];
    const uint32_t sb = smem_u32(smem);
    const int tid = threadIdx.x, lane = tid & 31, wid = tid >> 5;
    const int wm = wid & 3, wn = wid >> 2;
    const int m0 = blockIdx.y * 128, n0 = blockIdx.x * 128;

    float acc[2][8][4] = {};

    load_chunk(sb, 0, tid, Ahi, Alo, Bhi, Blo, m0, n0, 0, K);
    CP_COMMIT();

    for (int kc = 0; kc < nk; kc++) {
        if (kc + 1 < nk) {
            load_chunk(sb, (kc + 1) & 1, tid, Ahi, Alo, Bhi, Blo, m0, n0, kc + 1, K);
            CP_COMMIT();
            CP_WAIT(1);
        } else {
            CP_WAIT(0);
        }
        __syncthreads();

        const uint32_t st = sb + (kc & 1) * STG;
        #pragma unroll
        for (int ks = 0; ks < 4; ks++) {
            uint32_t a_hi[2][4], a_lo[2][4];
            {
                int acol = ks * 32 + (lane >> 4) * 16;
                #pragma unroll
                for (int mt = 0; mt < 2; mt++) {
                    int arow = wm * 32 + mt * 16 + (lane & 15);
                    uint32_t off = SW128((uint32_t)(arow * 128 + acol));
                    LDSM4(a_hi[mt], st + off);
                    LDSM4(a_lo[mt], st + SOFF_ALO + off);
                }
            }
            uint32_t b_hi[8][2], b_lo[8][2];
            {
                int bcol  = ks * 32 + ((lane >> 3) & 1) * 16;
                int brofs = (lane >> 4) * 8 + (lane & 7);
                #pragma unroll
                for (int nt2 = 0; nt2 < 4; nt2++) {
                    int brow = wn * 64 + nt2 * 16 + brofs;
                    uint32_t off = SW128((uint32_t)(brow * 128 + bcol));
                    uint32_t r[4];
                    LDSM4(r, st + SOFF_BHI + off);
                    b_hi[nt2*2][0]   = r[0]; b_hi[nt2*2][1]   = r[1];
                    b_hi[nt2*2+1][0] = r[2]; b_hi[nt2*2+1][1] = r[3];
                    LDSM4(r, st + SOFF_BLO + off);
                    b_lo[nt2*2][0]   = r[0]; b_lo[nt2*2][1]   = r[1];
                    b_lo[nt2*2+1][0] = r[2]; b_lo[nt2*2+1][1] = r[3];
                }
            }
            #pragma unroll
            for (int mt = 0; mt < 2; mt++)
                #pragma unroll
                for (int nt = 0; nt < 8; nt++) {
                    MMA(acc[mt][nt], a_hi[mt], b_hi[nt]);
                    MMA(acc[mt][nt], a_hi[mt], b_lo[nt]);
                    MMA(acc[mt][nt], a_lo[mt], b_hi[nt]);
                }
        }
        __syncthreads();
    }

    const int g = lane >> 2, tg = lane & 3;
    #pragma unroll
    for (int nt = 0; nt < 8; nt++) {
        int col = n0 + wn * 64 + nt * 8 + tg * 2;
        float b0 = bias[col], b1 = bias[col + 1];
        #pragma unroll
        for (int mt = 0; mt < 2; mt++) {
            int r0 = m0 + wm * 32 + mt * 16 + g;
            float2 v0 = make_float2(acc[mt][nt][0] + b0, acc[mt][nt][1] + b1);
            float2 v1 = make_float2(acc[mt][nt][2] + b0, acc[mt][nt][3] + b1);
            *reinterpret_cast<float2*>(C + (size_t)r0 * ldc + col)       = v0;
            *reinterpret_cast<float2*>(C + (size_t)(r0 + 8) * ldc + col) = v1;
        }
    }
}

// ---------------- grid barrier (release-arrive / acquire-poll) ----------------
__device__ __forceinline__ void gbarrier(int idx, unsigned G) {
    __syncthreads();
    if (threadIdx.x == 0) {
        unsigned a;
        asm volatile("atom.release.gpu.global.add.u32 %0, [%1], 1;"
                     : "=r"(a) : "l"(g_bar + idx) : "memory");
        if (a + 1u < G) {
            unsigned v;
            do {
                asm volatile("ld.acquire.gpu.global.u32 %0, [%1];"
                             : "=r"(v) : "l"(g_bar + idx) : "memory");
            } while (v < G);
        }
    }
    __syncthreads();
}

// ---------------- fp16 HMMA persistent scan (single-fp16 weights, full-state staging) ----------------
// 128 blocks x 256 threads. smem: WS1 32K | WS2 32K | STAGE 128K (no ring; RED aliased)
#define SC_WS1   0
#define SC_WS2   32768
#define SC_STAGE 65536
#define SC_TOTAL 196608

// phase1 staging: 64 rows x k128 chunk c -> STAGE + c*16K (no reuse)
__device__ __forceinline__ void stage1(uint32_t sb, int c, int tid, const __half* s)
{
    uint32_t base = sb + SC_STAGE + (uint32_t)c * 16384;
    #pragma unroll
    for (int j = 0; j < 4; j++) {
        int q = tid + j * 256;               // < 1024
        int sub = q >> 9, m = (q >> 3) & 63, kg = q & 7;
        uint32_t d = sub * 8192 + SW128((uint32_t)(m * 128 + kg * 16));
        size_t src = (size_t)m * 1024 + c * 128 + sub * 64 + kg * 8;
        CPA(base + d, s + src);
    }
}

// phase2 staging: 32 rows (m-half mh) x k128 chunk c -> STAGE + c*8K
__device__ __forceinline__ void stage2(uint32_t sb, int c, int tid, int mh, const __half* s)
{
    uint32_t base = sb + SC_STAGE + (uint32_t)c * 8192;
    #pragma unroll
    for (int j = 0; j < 2; j++) {
        int q = tid + j * 256;               // < 512
        int sub = q >> 8, m = (q >> 3) & 31, kg = q & 7;
        uint32_t d = sub * 4096 + SW128((uint32_t)(m * 128 + kg * 16));
        size_t src = (size_t)(mh * 32 + m) * 1024 + c * 128 + sub * 64 + kg * 8;
        CPA(base + d, s + src);
    }
}

__device__ __forceinline__ void mma_chunk1(uint32_t sb, int c, int lane, int mt, int kp,
                                           float acc[2][4])
{
    uint32_t sh = sb + SC_STAGE + (uint32_t)c * 16384 + kp * 8192;
    uint32_t wh = sb + SC_WS1 + (uint32_t)(c * 2 + kp) * 2048;
    uint32_t aoff0 = (uint32_t)((mt * 16 + (lane & 15)) * 128 + (lane >> 4) * 16);
    uint32_t boff0 = (uint32_t)((((lane >> 4) << 3) + (lane & 7)) * 128 + ((lane >> 3) & 1) * 16);
    #pragma unroll
    for (int ks = 0; ks < 4; ks++) {
        uint32_t offA = SW128(aoff0 + ks * 32);
        uint32_t offB = SW128(boff0 + ks * 32);
        uint32_t a[4], bh[4];
        LDSM4(a, sh + offA);
        LDSM4(bh, wh + offB);
        MMAH(acc[0], a, bh);
        MMAH(acc[1], a, bh + 2);
    }
}

__device__ __forceinline__ void mma_chunk2(uint32_t sb, int c, int lane, int mt2, int kq,
                                           float acc[2][4])
{
    uint32_t sh = sb + SC_STAGE + (uint32_t)c * 8192 + (kq >> 1) * 4096;
    uint32_t wh = sb + SC_WS2 + (uint32_t)(c * 2 + (kq >> 1)) * 2048;
    uint32_t aoff0 = (uint32_t)((mt2 * 16 + (lane & 15)) * 128 + (lane >> 4) * 16 + (kq & 1) * 64);
    uint32_t boff0 = (uint32_t)((((lane >> 4) << 3) + (lane & 7)) * 128
                              + ((lane >> 3) & 1) * 16 + (kq & 1) * 64);
    #pragma unroll
    for (int ks = 0; ks < 2; ks++) {
        uint32_t offA = SW128(aoff0 + ks * 32);
        uint32_t offB = SW128(boff0 + ks * 32);
        uint32_t a[4], bh[4];
        LDSM4(a, sh + offA);
        LDSM4(bh, wh + offB);
        MMAH(acc[0], a, bh);
        MMAH(acc[1], a, bh + 2);
    }
}

#define P1STEP(c, wcnt) do { \
    CP_WAIT(wcnt); __syncthreads(); \
    mma_chunk1(sb, (c), lane, mt, kp, acc); \
} while (0)

#define P2STEP(c, wcnt) do { \
    CP_WAIT(wcnt); __syncthreads(); \
    mma_chunk2(sb, (c), lane, mt2, kq, acc2); \
} while (0)

__global__ void __launch_bounds__(256, 1) k_scan() {
    extern __shared__ char sm[];
    const uint32_t sb = smem_u32(sm);
    float* redf = reinterpret_cast<float*>(sm + SC_STAGE);   // aliased over consumed chunk0
    const int tid = threadIdx.x, lane = tid & 31, w = tid >> 5;
    const int g = blockIdx.x;
    const unsigned G = gridDim.x;
    const bool isZ = (g >= 64);
    const int n0p1 = (g & 63) * 16;
    const int mh   = isZ ? 1 : 0;
    const int n0p2 = (g & 63) * 16;
    const int mt = w & 3, kp = w >> 2;       // phase1: 4 m-tiles x 2 k-halves
    const int mt2 = w & 1, kq = w >> 1;      // phase2: 2 m-tiles x 4 k-quarters
    const int gg = lane >> 2, tg = lane & 3;

    // ---- resident weights (single fp16, chunked [sc16][r16][k64]) ----
    {
        const __half* W1 = g_wH + (size_t)(isZ ? 1 : 0) * (Hh * Hh) + (size_t)n0p1 * 1024;
        const __half* W2 = g_wH + 2u * (Hh * Hh) + (size_t)n0p2 * 1024;
        #pragma unroll
        for (int j = 0; j < 8; j++) {
            int q = tid + j * 256;           // < 2048
            int sc = q >> 7, r = (q >> 3) & 15, kg = q & 7;
            uint32_t d = sc * 2048 + SW128((uint32_t)(r * 128 + kg * 16));
            size_t src = (size_t)r * 1024 + sc * 64 + kg * 8;
            CPA(sb + SC_WS1 + d, W1 + src);
            CPA(sb + SC_WS2 + d, W2 + src);
        }
    }
    CP_COMMIT();
    CP_WAIT(0);
    __syncthreads();

    const float* pre1 = g_pre + (isZ ? (size_t)BT * Hh : 0);
    const float* pre2 = g_pre + 2 * (size_t)BT * Hh;

    for (int t = 0; t < Tt; t++) {
        // prefetch phase1 epilogue operands
        float2 pv[2][2], hv[2][2];
        if (w < 4) {
            #pragma unroll
            for (int nt = 0; nt < 2; nt++)
                #pragma unroll
                for (int rr = 0; rr < 2; rr++) {
                    int m = mt * 16 + gg + rr * 8;
                    int n = n0p1 + nt * 8 + tg * 2;
                    pv[nt][rr] = *reinterpret_cast<const float2*>(&pre1[(size_t)(m * Tt + t) * Hh + n]);
                    if (!isZ) hv[nt][rr] = *reinterpret_cast<const float2*>(&g_h[m * 1024 + n]);
                }
        }

        // ======== phase 1: r / z (S = h @ W^T), 64 rows, 8 k128 chunks ========
        float acc[2][4] = {};
        #pragma unroll
        for (int c = 0; c < 8; c++) { stage1(sb, c, tid, g_sh); CP_COMMIT(); }
        P1STEP(0, 7); P1STEP(1, 6); P1STEP(2, 5); P1STEP(3, 4);
        P1STEP(4, 3); P1STEP(5, 2); P1STEP(6, 1); P1STEP(7, 0);
        __syncthreads();                      // chunk reads done before red (aliased) write
        if (w >= 4) {
            #pragma unroll
            for (int nt = 0; nt < 2; nt++)
                #pragma unroll
                for (int i = 0; i < 4; i++)
                    redf[mt * 256 + lane * 8 + nt * 4 + i] = acc[nt][i];
        }
        __syncthreads();
        // prefetch phase2 operands independent of phase1 output
        float2 pv2[2][2], hpv[2][2];
        if (w < 2) {
            #pragma unroll
            for (int nt = 0; nt < 2; nt++)
                #pragma unroll
                for (int rr = 0; rr < 2; rr++) {
                    int m = mh * 32 + mt2 * 16 + gg + rr * 8;
                    int n = n0p2 + nt * 8 + tg * 2;
                    pv2[nt][rr] = *reinterpret_cast<const float2*>(&pre2[(size_t)(m * Tt + t) * Hh + n]);
                    hpv[nt][rr] = *reinterpret_cast<const float2*>(&g_h[m * 1024 + n]);
                }
        }
        if (w < 4) {
            #pragma unroll
            for (int nt = 0; nt < 2; nt++) {
                #pragma unroll
                for (int i = 0; i < 4; i++)
                    acc[nt][i] += redf[mt * 256 + lane * 8 + nt * 4 + i];
                #pragma unroll
                for (int rr = 0; rr < 2; rr++) {
                    int m = mt * 16 + gg + rr * 8;
                    int n = n0p1 + nt * 8 + tg * 2;
                    float v0 = acc[nt][rr * 2 + 0] + pv[nt][rr].x;
                    float v1 = acc[nt][rr * 2 + 1] + pv[nt][rr].y;
                    float s0 = 1.f / (1.f + __expf(-v0));
                    float s1 = 1.f / (1.f + __expf(-v1));
                    if (!isZ) {
                        float rh0 = s0 * hv[nt][rr].x, rh1 = s1 * hv[nt][rr].y;
                        *reinterpret_cast<__half2*>(&g_rh[m * 1024 + n]) =
                            __floats2half2_rn(rh0, rh1);
                    } else {
                        *reinterpret_cast<float2*>(&g_zz[m * 1024 + n]) = make_float2(s0, s1);
                    }
                }
            }
        }
        gbarrier(2 * t, G);

        // ======== phase 2: hbar + update, 32 rows (m-half), 8 k128 chunks ========
        {
            float2 zv[2][2];
            if (w < 2) {
                #pragma unroll
                for (int nt = 0; nt < 2; nt++)
                    #pragma unroll
                    for (int rr = 0; rr < 2; rr++) {
                        int m = mh * 32 + mt2 * 16 + gg + rr * 8;
                        int n = n0p2 + nt * 8 + tg * 2;
                        zv[nt][rr] = *reinterpret_cast<const float2*>(&g_zz[m * 1024 + n]);
                    }
            }
            float acc2[2][4] = {};
            #pragma unroll
            for (int c = 0; c < 8; c++) { stage2(sb, c, tid, mh, g_rh); CP_COMMIT(); }
            P2STEP(0, 7); P2STEP(1, 6); P2STEP(2, 5); P2STEP(3, 4);
            P2STEP(4, 3); P2STEP(5, 2); P2STEP(6, 1); P2STEP(7, 0);
            __syncthreads();
            if (kq > 0) {                     // warps 2-7 write partials
                int slot = (kq - 1) * 2 + mt2;
                #pragma unroll
                for (int nt = 0; nt < 2; nt++)
                    #pragma unroll
                    for (int i = 0; i < 4; i++)
                        redf[slot * 256 + lane * 8 + nt * 4 + i] = acc2[nt][i];
            }
            __syncthreads();
            if (w < 2) {
                #pragma unroll
                for (int q2 = 0; q2 < 3; q2++)
                    #pragma unroll
                    for (int nt = 0; nt < 2; nt++)
                        #pragma unroll
                        for (int i = 0; i < 4; i++)
                            acc2[nt][i] += redf[(q2 * 2 + mt2) * 256 + lane * 8 + nt * 4 + i];
                #pragma unroll
                for (int nt = 0; nt < 2; nt++) {
                    #pragma unroll
                    for (int rr = 0; rr < 2; rr++) {
                        int m = mh * 32 + mt2 * 16 + gg + rr * 8;
                        int n = n0p2 + nt * 8 + tg * 2;
                        float hb0 = tanhf(acc2[nt][rr * 2 + 0] + pv2[nt][rr].x);
                        float hb1 = tanhf(acc2[nt][rr * 2 + 1] + pv2[nt][rr].y);
                        float hn0 = fmaf(zv[nt][rr].x, hb0 - hpv[nt][rr].x, hpv[nt][rr].x);
                        float hn1 = fmaf(zv[nt][rr].y, hb1 - hpv[nt][rr].y, hpv[nt][rr].y);
                        *reinterpret_cast<float2*>(&g_h[m * 1024 + n]) = make_float2(hn0, hn1);
                        *reinterpret_cast<__half2*>(&g_sh[m * 1024 + n]) =
                            __floats2half2_rn(hn0, hn1);
                        __nv_bfloat162 hi2, lo2;
                        split2(hn0, hn1, &hi2, &lo2);
                        size_t ho = (size_t)(m * Tt + t) * Hh + n;
                        *reinterpret_cast<__nv_bfloat162*>(&g_hhi[ho]) = hi2;
                        *reinterpret_cast<__nv_bfloat162*>(&g_hlo[ho]) = lo2;
                    }
                }
            }
        }
        gbarrier(2 * t + 1, G);
    }
}

// ---------------- launch ----------------
extern "C" void kernel_launch(void* const* d_in, const int* in_sizes, int n_in,
                              void* d_out, int out_size)
{
    const int*   x     = (const int*)  d_in[0];
    const float* start = (const float*)d_in[1];
    const float* wte   = (const float*)d_in[2];
    const float* Wr    = (const float*)d_in[3];
    const float* br    = (const float*)d_in[4];
    const float* Wbar  = (const float*)d_in[5];
    const float* bbar  = (const float*)d_in[6];
    const float* Wz    = (const float*)d_in[7];
    const float* bz    = (const float*)d_in[8];
    const float* Whead = (const float*)d_in[9];
    const float* bhead = (const float*)d_in[10];
    float* out = (float*)d_out;

    float* p_pre;
    __nv_bfloat16 *p_ehi, *p_elo, *p_hhi, *p_hlo, *p_wchi, *p_wclo, *p_whhi, *p_whlo;
    cudaGetSymbolAddress((void**)&p_pre,  g_pre);
    cudaGetSymbolAddress((void**)&p_ehi,  g_ehi);   cudaGetSymbolAddress((void**)&p_elo,  g_elo);
    cudaGetSymbolAddress((void**)&p_hhi,  g_hhi);   cudaGetSymbolAddress((void**)&p_hlo,  g_hlo);
    cudaGetSymbolAddress((void**)&p_wchi, g_wchi);  cudaGetSymbolAddress((void**)&p_wclo, g_wclo);
    cudaGetSymbolAddress((void**)&p_whhi, g_whhi);  cudaGetSymbolAddress((void**)&p_whlo, g_whlo);

    cudaFuncSetAttribute(k_scan,  cudaFuncAttributeMaxDynamicSharedMemorySize, SC_TOTAL);
    cudaFuncSetAttribute(k_tgemm, cudaFuncAttributeMaxDynamicSharedMemorySize, SM_TOTAL);

    k_init<<<256, 256>>>(start);
    k_embed<<<(BT * Ee / 4) / 256, 256>>>(x, wte);
    k_cvt_wcat<<<(3 * Hh * Ee) / 256, 256>>>(Wr, Wz, Wbar);
    k_cvt_wH<<<(3 * Hh * Hh) / 256, 256>>>(Wr, Wz, Wbar);
    k_cvt<<<(Vv * Hh / 4) / 256, 256>>>(Whead, p_whhi, p_whlo);

    // pre-projections: 3 gates, N=1024 each, K=512
    for (int gate = 0; gate < 3; gate++) {
        const float* bias = (gate == 0) ? br : (gate == 1) ? bz : bbar;
        k_tgemm<<<dim3(Hh/128, BT/128), 256, SM_TOTAL>>>(
            p_ehi, p_elo,
            p_wchi + (size_t)gate * Hh * Ee, p_wclo + (size_t)gate * Hh * Ee,
            bias, p_pre + (size_t)gate * BT * Hh, Ee, Hh, Ee/64);
    }

    k_scan<<<128, 256, SC_TOTAL>>>();

    k_tgemm<<<dim3(Vv/128, BT/128), 256, SM_TOTAL>>>(
        p_hhi, p_hlo, p_whhi, p_whlo, bhead, out, Hh, Vv, Hh/64);
}

// round 17
// speedup vs baseline: 1.1447x; 1.1055x over previous
#include <cuda_runtime.h>
#include <cuda_bf16.h>
#include <cuda_fp16.h>
#include <math.h>
#include <stdint.h>

#define Bz   64
#define Tt   256
#define Vv   4096
#define Ee   512
#define Hh   1024
#define BT   (Bz*Tt)
#define CAT  (Ee+Hh)

// ---------------- static device scratch ----------------
__device__ float          g_pre[3u * BT * Hh];     // [gate][bt][n] gate 0=r,1=z,2=hbar
__device__ float          g_h[Bz * Hh];            // fp32 state [m][n]
__device__ float          g_zz[Bz * Hh];           // z [m][n]
__device__ __half         g_sh[Bz * Hh];           // fp16 state [m][k]
__device__ __half         g_rh[Bz * Hh];           // fp16 r*h [m][k]
__device__ unsigned       g_bar[1024];
__device__ __nv_bfloat16  g_ehi[BT * Ee];
__device__ __nv_bfloat16  g_elo[BT * Ee];
__device__ __half         g_hid[BT * Hh];          // hidden (head input, fp16) [bt][k]
__device__ __nv_bfloat16  g_wchi[3 * Hh * Ee];     // gate weights E-part [3072][512]
__device__ __nv_bfloat16  g_wclo[3 * Hh * Ee];
__device__ __half         g_wH[3u * Hh * Hh];      // gate weights H-part fp16 (single)
__device__ __half         g_whhi[Vv * Hh];         // head weights fp16 hi/lo
__device__ __half         g_whlo[Vv * Hh];

// ---------------- helpers ----------------
__device__ __forceinline__ uint32_t smem_u32(const void* p) {
    uint32_t a;
    asm("{ .reg .u64 t; cvta.to.shared.u64 t, %1; cvt.u32.u64 %0, t; }" : "=r"(a) : "l"(p));
    return a;
}
#define CP_COMMIT() asm volatile("cp.async.commit_group;" ::: "memory")
#define CP_WAIT(n)  asm volatile("cp.async.wait_group %0;" :: "n"(n) : "memory")
#define CPA(dst, src) \
    asm volatile("cp.async.cg.shared.global [%0], [%1], 16;" :: "r"(dst), "l"(src) : "memory")
#define SW128(x) ((x) ^ (((x) >> 3) & 0x70))

#define LDSM4(r, addr) \
    asm volatile("ldmatrix.sync.aligned.m8n8.x4.shared.b16 {%0,%1,%2,%3}, [%4];" \
        : "=r"((r)[0]), "=r"((r)[1]), "=r"((r)[2]), "=r"((r)[3]) : "r"(addr))

#define MMA(d, a, b) \
    asm volatile("mma.sync.aligned.m16n8k16.row.col.f32.bf16.bf16.f32 " \
        "{%0,%1,%2,%3}, {%4,%5,%6,%7}, {%8,%9}, {%0,%1,%2,%3};" \
        : "+f"((d)[0]), "+f"((d)[1]), "+f"((d)[2]), "+f"((d)[3]) \
        : "r"((a)[0]), "r"((a)[1]), "r"((a)[2]), "r"((a)[3]), "r"((b)[0]), "r"((b)[1]))

#define MMAH(d, a, b) \
    asm volatile("mma.sync.aligned.m16n8k16.row.col.f32.f16.f16.f32 " \
        "{%0,%1,%2,%3}, {%4,%5,%6,%7}, {%8,%9}, {%0,%1,%2,%3};" \
        : "+f"((d)[0]), "+f"((d)[1]), "+f"((d)[2]), "+f"((d)[3]) \
        : "r"((a)[0]), "r"((a)[1]), "r"((a)[2]), "r"((a)[3]), "r"((b)[0]), "r"((b)[1]))

__device__ __forceinline__ void split2(float a, float b, __nv_bfloat162* hi, __nv_bfloat162* lo) {
    __nv_bfloat16 ah = __float2bfloat16(a), bh = __float2bfloat16(b);
    *hi = __nv_bfloat162(ah, bh);
    *lo = __nv_bfloat162(__float2bfloat16(a - __bfloat162float(ah)),
                         __float2bfloat16(b - __bfloat162float(bh)));
}

// ---------------- init / embed / converters ----------------
__global__ void k_init(const float* __restrict__ start) {
    int i = blockIdx.x * blockDim.x + threadIdx.x;   // 65536
    float v = start[i & 1023];
    g_h[i] = v;
    g_sh[i] = __float2half_rn(v);
    if (i < 1024) g_bar[i] = 0u;
}
__global__ void k_embed(const int* __restrict__ x, const float* __restrict__ wte) {
    int i  = blockIdx.x * blockDim.x + threadIdx.x;
    int bt = i >> 7, e4 = i & 127;
    int tok = x[bt];
    float4 v = reinterpret_cast<const float4*>(wte + (size_t)tok * Ee)[e4];
    __nv_bfloat162 h0, l0, h1, l1;
    split2(v.x, v.y, &h0, &l0); split2(v.z, v.w, &h1, &l1);
    reinterpret_cast<__nv_bfloat162*>(g_ehi)[2*i]   = h0;
    reinterpret_cast<__nv_bfloat162*>(g_ehi)[2*i+1] = h1;
    reinterpret_cast<__nv_bfloat162*>(g_elo)[2*i]   = l0;
    reinterpret_cast<__nv_bfloat162*>(g_elo)[2*i+1] = l1;
}
__global__ void k_cvt_wcat(const float* __restrict__ Wr, const float* __restrict__ Wz,
                           const float* __restrict__ Wbar) {
    int i = blockIdx.x * blockDim.x + threadIdx.x;    // 3072*512
    int row = i >> 9, col = i & 511;
    const float* W = (row < 1024) ? Wr : (row < 2048) ? Wz : Wbar;
    float v = W[(size_t)(row & 1023) * CAT + col];
    __nv_bfloat16 h = __float2bfloat16(v);
    g_wchi[i] = h;
    g_wclo[i] = __float2bfloat16(v - __bfloat162float(h));
}
__global__ void k_cvt_wH(const float* __restrict__ Wr, const float* __restrict__ Wz,
                         const float* __restrict__ Wbar) {
    int i = blockIdx.x * blockDim.x + threadIdx.x;    // 3*1024*1024
    int gate = i >> 20, row = (i >> 10) & 1023, col = i & 1023;
    const float* W = (gate == 0) ? Wr : (gate == 1) ? Wz : Wbar;
    g_wH[i] = __float2half_rn(W[(size_t)row * CAT + Ee + col]);
}
__global__ void k_cvt_whead(const float* __restrict__ Whead) {
    int i = blockIdx.x * blockDim.x + threadIdx.x;    // Vv*Hh
    float v = Whead[i];
    __half h = __float2half_rn(v);
    g_whhi[i] = h;
    g_whlo[i] = __float2half_rn(v - __half2float(h));
}

// ---------------- split-bf16 HMMA GEMM (pre-projections) ----------------
#define STG      65536
#define SOFF_ALO 16384
#define SOFF_BHI 32768
#define SOFF_BLO 49152
#define SM_TOTAL 131072

__device__ __forceinline__ void load_chunk(
    uint32_t sb, int s, int tid,
    const __nv_bfloat16* Ahi, const __nv_bfloat16* Alo,
    const __nv_bfloat16* Bhi, const __nv_bfloat16* Blo,
    int m0, int n0, int kc, int K)
{
    uint32_t st = sb + s * STG;
    int kb = kc * 64;
    #pragma unroll
    for (int j = 0; j < 4; j++) {
        int q = tid + j * 256, row = q >> 3, kg = q & 7;
        uint32_t d = SW128((uint32_t)(row * 128 + kg * 16));
        size_t srcA = (size_t)(m0 + row) * K + kb + kg * 8;
        size_t srcB = (size_t)(n0 + row) * K + kb + kg * 8;
        CPA(st + d,            Ahi + srcA);
        CPA(st + SOFF_ALO + d, Alo + srcA);
        CPA(st + SOFF_BHI + d, Bhi + srcB);
        CPA(st + SOFF_BLO + d, Blo + srcB);
    }
}

__global__ void __launch_bounds__(256, 1) k_tgemm(
    const __nv_bfloat16* __restrict__ Ahi, const __nv_bfloat16* __restrict__ Alo,
    const __nv_bfloat16* __restrict__ Bhi, const __nv_bfloat16* __restrict__ Blo,
    const float* __restrict__ bias, float* __restrict__ C, int K, int ldc, int nk)
{
    extern __shared__ char smem[];
    const uint32_t sb = smem_u32(smem);
    const int tid = threadIdx.x, lane = tid & 31, wid = tid >> 5;
    const int wm = wid & 3, wn = wid >> 2;
    const int m0 = blockIdx.y * 128, n0 = blockIdx.x * 128;

    float acc[2][8][4] = {};

    load_chunk(sb, 0, tid, Ahi, Alo, Bhi, Blo, m0, n0, 0, K);
    CP_COMMIT();

    for (int kc = 0; kc < nk; kc++) {
        if (kc + 1 < nk) {
            load_chunk(sb, (kc + 1) & 1, tid, Ahi, Alo, Bhi, Blo, m0, n0, kc + 1, K);
            CP_COMMIT();
            CP_WAIT(1);
        } else {
            CP_WAIT(0);
        }
        __syncthreads();

        const uint32_t st = sb + (kc & 1) * STG;
        #pragma unroll
        for (int ks = 0; ks < 4; ks++) {
            uint32_t a_hi[2][4], a_lo[2][4];
            {
                int acol = ks * 32 + (lane >> 4) * 16;
                #pragma unroll
                for (int mt = 0; mt < 2; mt++) {
                    int arow = wm * 32 + mt * 16 + (lane & 15);
                    uint32_t off = SW128((uint32_t)(arow * 128 + acol));
                    LDSM4(a_hi[mt], st + off);
                    LDSM4(a_lo[mt], st + SOFF_ALO + off);
                }
            }
            uint32_t b_hi[8][2], b_lo[8][2];
            {
                int bcol  = ks * 32 + ((lane >> 3) & 1) * 16;
                int brofs = (lane >> 4) * 8 + (lane & 7);
                #pragma unroll
                for (int nt2 = 0; nt2 < 4; nt2++) {
                    int brow = wn * 64 + nt2 * 16 + brofs;
                    uint32_t off = SW128((uint32_t)(brow * 128 + bcol));
                    uint32_t r[4];
                    LDSM4(r, st + SOFF_BHI + off);
                    b_hi[nt2*2][0]   = r[0]; b_hi[nt2*2][1]   = r[1];
                    b_hi[nt2*2+1][0] = r[2]; b_hi[nt2*2+1][1] = r[3];
                    LDSM4(r, st + SOFF_BLO + off);
                    b_lo[nt2*2][0]   = r[0]; b_lo[nt2*2][1]   = r[1];
                    b_lo[nt2*2+1][0] = r[2]; b_lo[nt2*2+1][1] = r[3];
                }
            }
            #pragma unroll
            for (int mt = 0; mt < 2; mt++)
                #pragma unroll
                for (int nt = 0; nt < 8; nt++) {
                    MMA(acc[mt][nt], a_hi[mt], b_hi[nt]);
                    MMA(acc[mt][nt], a_hi[mt], b_lo[nt]);
                    MMA(acc[mt][nt], a_lo[mt], b_hi[nt]);
                }
        }
        __syncthreads();
    }

    const int g = lane >> 2, tg = lane & 3;
    #pragma unroll
    for (int nt = 0; nt < 8; nt++) {
        int col = n0 + wn * 64 + nt * 8 + tg * 2;
        float b0 = bias[col], b1 = bias[col + 1];
        #pragma unroll
        for (int mt = 0; mt < 2; mt++) {
            int r0 = m0 + wm * 32 + mt * 16 + g;
            float2 v0 = make_float2(acc[mt][nt][0] + b0, acc[mt][nt][1] + b1);
            float2 v1 = make_float2(acc[mt][nt][2] + b0, acc[mt][nt][3] + b1);
            *reinterpret_cast<float2*>(C + (size_t)r0 * ldc + col)       = v0;
            *reinterpret_cast<float2*>(C + (size_t)(r0 + 8) * ldc + col) = v1;
        }
    }
}

// ---------------- fp16 head GEMM: A fp16 single, B fp16 hi/lo, 2-pass ----------------
#define HSTG      49152
#define HOFF_BHI  16384
#define HOFF_BLO  32768
#define SMH_TOTAL 98304

__device__ __forceinline__ void load_chunk_h(
    uint32_t sb, int s, int tid,
    const __half* A, const __half* Bhi, const __half* Blo,
    int m0, int n0, int kc, int K)
{
    uint32_t st = sb + s * HSTG;
    int kb = kc * 64;
    #pragma unroll
    for (int j = 0; j < 4; j++) {
        int q = tid + j * 256, row = q >> 3, kg = q & 7;
        uint32_t d = SW128((uint32_t)(row * 128 + kg * 16));
        size_t srcA = (size_t)(m0 + row) * K + kb + kg * 8;
        size_t srcB = (size_t)(n0 + row) * K + kb + kg * 8;
        CPA(st + d,            A   + srcA);
        CPA(st + HOFF_BHI + d, Bhi + srcB);
        CPA(st + HOFF_BLO + d, Blo + srcB);
    }
}

__global__ void __launch_bounds__(256, 1) k_tgemm_head(
    const __half* __restrict__ A, const __half* __restrict__ Bhi,
    const __half* __restrict__ Blo,
    const float* __restrict__ bias, float* __restrict__ C, int K, int ldc, int nk)
{
    extern __shared__ char smem[];
    const uint32_t sb = smem_u32(smem);
    const int tid = threadIdx.x, lane = tid & 31, wid = tid >> 5;
    const int wm = wid & 3, wn = wid >> 2;
    const int m0 = blockIdx.y * 128, n0 = blockIdx.x * 128;

    float acc[2][8][4] = {};

    load_chunk_h(sb, 0, tid, A, Bhi, Blo, m0, n0, 0, K);
    CP_COMMIT();

    for (int kc = 0; kc < nk; kc++) {
        if (kc + 1 < nk) {
            load_chunk_h(sb, (kc + 1) & 1, tid, A, Bhi, Blo, m0, n0, kc + 1, K);
            CP_COMMIT();
            CP_WAIT(1);
        } else {
            CP_WAIT(0);
        }
        __syncthreads();

        const uint32_t st = sb + (kc & 1) * HSTG;
        #pragma unroll
        for (int ks = 0; ks < 4; ks++) {
            uint32_t a[2][4];
            {
                int acol = ks * 32 + (lane >> 4) * 16;
                #pragma unroll
                for (int mt = 0; mt < 2; mt++) {
                    int arow = wm * 32 + mt * 16 + (lane & 15);
                    uint32_t off = SW128((uint32_t)(arow * 128 + acol));
                    LDSM4(a[mt], st + off);
                }
            }
            uint32_t b_hi[8][2], b_lo[8][2];
            {
                int bcol  = ks * 32 + ((lane >> 3) & 1) * 16;
                int brofs = (lane >> 4) * 8 + (lane & 7);
                #pragma unroll
                for (int nt2 = 0; nt2 < 4; nt2++) {
                    int brow = wn * 64 + nt2 * 16 + brofs;
                    uint32_t off = SW128((uint32_t)(brow * 128 + bcol));
                    uint32_t r[4];
                    LDSM4(r, st + HOFF_BHI + off);
                    b_hi[nt2*2][0]   = r[0]; b_hi[nt2*2][1]   = r[1];
                    b_hi[nt2*2+1][0] = r[2]; b_hi[nt2*2+1][1] = r[3];
                    LDSM4(r, st + HOFF_BLO + off);
                    b_lo[nt2*2][0]   = r[0]; b_lo[nt2*2][1]   = r[1];
                    b_lo[nt2*2+1][0] = r[2]; b_lo[nt2*2+1][1] = r[3];
                }
            }
            #pragma unroll
            for (int mt = 0; mt < 2; mt++)
                #pragma unroll
                for (int nt = 0; nt < 8; nt++) {
                    MMAH(acc[mt][nt], a[mt], b_hi[nt]);
                    MMAH(acc[mt][nt], a[mt], b_lo[nt]);
                }
        }
        __syncthreads();
    }

    const int g = lane >> 2, tg = lane & 3;
    #pragma unroll
    for (int nt = 0; nt < 8; nt++) {
        int col = n0 + wn * 64 + nt * 8 + tg * 2;
        float b0 = bias[col], b1 = bias[col + 1];
        #pragma unroll
        for (int mt = 0; mt < 2; mt++) {
            int r0 = m0 + wm * 32 + mt * 16 + g;
            float2 v0 = make_float2(acc[mt][nt][0] + b0, acc[mt][nt][1] + b1);
            float2 v1 = make_float2(acc[mt][nt][2] + b0, acc[mt][nt][3] + b1);
            *reinterpret_cast<float2*>(C + (size_t)r0 * ldc + col)       = v0;
            *reinterpret_cast<float2*>(C + (size_t)(r0 + 8) * ldc + col) = v1;
        }
    }
}

// ---------------- grid barrier (release-arrive / acquire-poll) ----------------
__device__ __forceinline__ void gbarrier(int idx, unsigned G) {
    __syncthreads();
    if (threadIdx.x == 0) {
        unsigned a;
        asm volatile("atom.release.gpu.global.add.u32 %0, [%1], 1;"
                     : "=r"(a) : "l"(g_bar + idx) : "memory");
        if (a + 1u < G) {
            unsigned v;
            do {
                asm volatile("ld.acquire.gpu.global.u32 %0, [%1];"
                             : "=r"(v) : "l"(g_bar + idx) : "memory");
            } while (v < G);
        }
    }
    __syncthreads();
}

// ---------------- fp16 HMMA persistent scan (R13 structure, frozen) ----------------
// 128 blocks x 256 threads. smem: WS1 32K | WS2 32K | STAGE 128K (no ring; RED aliased)
#define SC_WS1   0
#define SC_WS2   32768
#define SC_STAGE 65536
#define SC_TOTAL 196608

__device__ __forceinline__ void stage1(uint32_t sb, int c, int tid, const __half* s)
{
    uint32_t base = sb + SC_STAGE + (uint32_t)c * 16384;
    #pragma unroll
    for (int j = 0; j < 4; j++) {
        int q = tid + j * 256;               // < 1024
        int sub = q >> 9, m = (q >> 3) & 63, kg = q & 7;
        uint32_t d = sub * 8192 + SW128((uint32_t)(m * 128 + kg * 16));
        size_t src = (size_t)m * 1024 + c * 128 + sub * 64 + kg * 8;
        CPA(base + d, s + src);
    }
}

__device__ __forceinline__ void stage2(uint32_t sb, int c, int tid, int mh, const __half* s)
{
    uint32_t base = sb + SC_STAGE + (uint32_t)c * 8192;
    #pragma unroll
    for (int j = 0; j < 2; j++) {
        int q = tid + j * 256;               // < 512
        int sub = q >> 8, m = (q >> 3) & 31, kg = q & 7;
        uint32_t d = sub * 4096 + SW128((uint32_t)(m * 128 + kg * 16));
        size_t src = (size_t)(mh * 32 + m) * 1024 + c * 128 + sub * 64 + kg * 8;
        CPA(base + d, s + src);
    }
}

__device__ __forceinline__ void mma_chunk1(uint32_t sb, int c, int lane, int mt, int kp,
                                           float acc[2][4])
{
    uint32_t sh = sb + SC_STAGE + (uint32_t)c * 16384 + kp * 8192;
    uint32_t wh = sb + SC_WS1 + (uint32_t)(c * 2 + kp) * 2048;
    uint32_t aoff0 = (uint32_t)((mt * 16 + (lane & 15)) * 128 + (lane >> 4) * 16);
    uint32_t boff0 = (uint32_t)((((lane >> 4) << 3) + (lane & 7)) * 128 + ((lane >> 3) & 1) * 16);
    #pragma unroll
    for (int ks = 0; ks < 4; ks++) {
        uint32_t offA = SW128(aoff0 + ks * 32);
        uint32_t offB = SW128(boff0 + ks * 32);
        uint32_t a[4], bh[4];
        LDSM4(a, sh + offA);
        LDSM4(bh, wh + offB);
        MMAH(acc[0], a, bh);
        MMAH(acc[1], a, bh + 2);
    }
}

__device__ __forceinline__ void mma_chunk2(uint32_t sb, int c, int lane, int mt2, int kq,
                                           float acc[2][4])
{
    uint32_t sh = sb + SC_STAGE + (uint32_t)c * 8192 + (kq >> 1) * 4096;
    uint32_t wh = sb + SC_WS2 + (uint32_t)(c * 2 + (kq >> 1)) * 2048;
    uint32_t aoff0 = (uint32_t)((mt2 * 16 + (lane & 15)) * 128 + (lane >> 4) * 16 + (kq & 1) * 64);
    uint32_t boff0 = (uint32_t)((((lane >> 4) << 3) + (lane & 7)) * 128
                              + ((lane >> 3) & 1) * 16 + (kq & 1) * 64);
    #pragma unroll
    for (int ks = 0; ks < 2; ks++) {
        uint32_t offA = SW128(aoff0 + ks * 32);
        uint32_t offB = SW128(boff0 + ks * 32);
        uint32_t a[4], bh[4];
        LDSM4(a, sh + offA);
        LDSM4(bh, wh + offB);
        MMAH(acc[0], a, bh);
        MMAH(acc[1], a, bh + 2);
    }
}

#define P1STEP(c, wcnt) do { \
    CP_WAIT(wcnt); __syncthreads(); \
    mma_chunk1(sb, (c), lane, mt, kp, acc); \
} while (0)

#define P2STEP(c, wcnt) do { \
    CP_WAIT(wcnt); __syncthreads(); \
    mma_chunk2(sb, (c), lane, mt2, kq, acc2); \
} while (0)

__global__ void __launch_bounds__(256, 1) k_scan() {
    extern __shared__ char sm[];
    const uint32_t sb = smem_u32(sm);
    float* redf = reinterpret_cast<float*>(sm + SC_STAGE);   // aliased over consumed chunk0
    const int tid = threadIdx.x, lane = tid & 31, w = tid >> 5;
    const int g = blockIdx.x;
    const unsigned G = gridDim.x;
    const bool isZ = (g >= 64);
    const int n0p1 = (g & 63) * 16;
    const int mh   = isZ ? 1 : 0;
    const int n0p2 = (g & 63) * 16;
    const int mt = w & 3, kp = w >> 2;       // phase1: 4 m-tiles x 2 k-halves
    const int mt2 = w & 1, kq = w >> 1;      // phase2: 2 m-tiles x 4 k-quarters
    const int gg = lane >> 2, tg = lane & 3;

    // ---- resident weights (single fp16, chunked [sc16][r16][k64]) ----
    {
        const __half* W1 = g_wH + (size_t)(isZ ? 1 : 0) * (Hh * Hh) + (size_t)n0p1 * 1024;
        const __half* W2 = g_wH + 2u * (Hh * Hh) + (size_t)n0p2 * 1024;
        #pragma unroll
        for (int j = 0; j < 8; j++) {
            int q = tid + j * 256;           // < 2048
            int sc = q >> 7, r = (q >> 3) & 15, kg = q & 7;
            uint32_t d = sc * 2048 + SW128((uint32_t)(r * 128 + kg * 16));
            size_t src = (size_t)r * 1024 + sc * 64 + kg * 8;
            CPA(sb + SC_WS1 + d, W1 + src);
            CPA(sb + SC_WS2 + d, W2 + src);
        }
    }
    CP_COMMIT();
    CP_WAIT(0);
    __syncthreads();

    const float* pre1 = g_pre + (isZ ? (size_t)BT * Hh : 0);
    const float* pre2 = g_pre + 2 * (size_t)BT * Hh;

    for (int t = 0; t < Tt; t++) {
        // prefetch phase1 epilogue operands
        float2 pv[2][2], hv[2][2];
        if (w < 4) {
            #pragma unroll
            for (int nt = 0; nt < 2; nt++)
                #pragma unroll
                for (int rr = 0; rr < 2; rr++) {
                    int m = mt * 16 + gg + rr * 8;
                    int n = n0p1 + nt * 8 + tg * 2;
                    pv[nt][rr] = *reinterpret_cast<const float2*>(&pre1[(size_t)(m * Tt + t) * Hh + n]);
                    if (!isZ) hv[nt][rr] = *reinterpret_cast<const float2*>(&g_h[m * 1024 + n]);
                }
        }

        // ======== phase 1: r / z (S = h @ W^T), 64 rows, 8 k128 chunks ========
        float acc[2][4] = {};
        #pragma unroll
        for (int c = 0; c < 8; c++) { stage1(sb, c, tid, g_sh); CP_COMMIT(); }
        P1STEP(0, 7); P1STEP(1, 6); P1STEP(2, 5); P1STEP(3, 4);
        P1STEP(4, 3); P1STEP(5, 2); P1STEP(6, 1); P1STEP(7, 0);
        __syncthreads();                      // chunk reads done before red (aliased) write
        if (w >= 4) {
            #pragma unroll
            for (int nt = 0; nt < 2; nt++)
                #pragma unroll
                for (int i = 0; i < 4; i++)
                    redf[mt * 256 + lane * 8 + nt * 4 + i] = acc[nt][i];
        }
        __syncthreads();
        // prefetch phase2 operands independent of phase1 output
        float2 pv2[2][2], hpv[2][2];
        if (w < 2) {
            #pragma unroll
            for (int nt = 0; nt < 2; nt++)
                #pragma unroll
                for (int rr = 0; rr < 2; rr++) {
                    int m = mh * 32 + mt2 * 16 + gg + rr * 8;
                    int n = n0p2 + nt * 8 + tg * 2;
                    pv2[nt][rr] = *reinterpret_cast<const float2*>(&pre2[(size_t)(m * Tt + t) * Hh + n]);
                    hpv[nt][rr] = *reinterpret_cast<const float2*>(&g_h[m * 1024 + n]);
                }
        }
        if (w < 4) {
            #pragma unroll
            for (int nt = 0; nt < 2; nt++) {
                #pragma unroll
                for (int i = 0; i < 4; i++)
                    acc[nt][i] += redf[mt * 256 + lane * 8 + nt * 4 + i];
                #pragma unroll
                for (int rr = 0; rr < 2; rr++) {
                    int m = mt * 16 + gg + rr * 8;
                    int n = n0p1 + nt * 8 + tg * 2;
                    float v0 = acc[nt][rr * 2 + 0] + pv[nt][rr].x;
                    float v1 = acc[nt][rr * 2 + 1] + pv[nt][rr].y;
                    float s0 = 1.f / (1.f + __expf(-v0));
                    float s1 = 1.f / (1.f + __expf(-v1));
                    if (!isZ) {
                        float rh0 = s0 * hv[nt][rr].x, rh1 = s1 * hv[nt][rr].y;
                        *reinterpret_cast<__half2*>(&g_rh[m * 1024 + n]) =
                            __floats2half2_rn(rh0, rh1);
                    } else {
                        *reinterpret_cast<float2*>(&g_zz[m * 1024 + n]) = make_float2(s0, s1);
                    }
                }
            }
        }
        gbarrier(2 * t, G);

        // ======== phase 2: hbar + update, 32 rows (m-half), 8 k128 chunks ========
        {
            float2 zv[2][2];
            if (w < 2) {
                #pragma unroll
                for (int nt = 0; nt < 2; nt++)
                    #pragma unroll
                    for (int rr = 0; rr < 2; rr++) {
                        int m = mh * 32 + mt2 * 16 + gg + rr * 8;
                        int n = n0p2 + nt * 8 + tg * 2;
                        zv[nt][rr] = *reinterpret_cast<const float2*>(&g_zz[m * 1024 + n]);
                    }
            }
            float acc2[2][4] = {};
            #pragma unroll
            for (int c = 0; c < 8; c++) { stage2(sb, c, tid, mh, g_rh); CP_COMMIT(); }
            P2STEP(0, 7); P2STEP(1, 6); P2STEP(2, 5); P2STEP(3, 4);
            P2STEP(4, 3); P2STEP(5, 2); P2STEP(6, 1); P2STEP(7, 0);
            __syncthreads();
            if (kq > 0) {                     // warps 2-7 write partials
                int slot = (kq - 1) * 2 + mt2;
                #pragma unroll
                for (int nt = 0; nt < 2; nt++)
                    #pragma unroll
                    for (int i = 0; i < 4; i++)
                        redf[slot * 256 + lane * 8 + nt * 4 + i] = acc2[nt][i];
            }
            __syncthreads();
            if (w < 2) {
                #pragma unroll
                for (int q2 = 0; q2 < 3; q2++)
                    #pragma unroll
                    for (int nt = 0; nt < 2; nt++)
                        #pragma unroll
                        for (int i = 0; i < 4; i++)
                            acc2[nt][i] += redf[(q2 * 2 + mt2) * 256 + lane * 8 + nt * 4 + i];
                #pragma unroll
                for (int nt = 0; nt < 2; nt++) {
                    #pragma unroll
                    for (int rr = 0; rr < 2; rr++) {
                        int m = mh * 32 + mt2 * 16 + gg + rr * 8;
                        int n = n0p2 + nt * 8 + tg * 2;
                        float hb0 = tanhf(acc2[nt][rr * 2 + 0] + pv2[nt][rr].x);
                        float hb1 = tanhf(acc2[nt][rr * 2 + 1] + pv2[nt][rr].y);
                        float hn0 = fmaf(zv[nt][rr].x, hb0 - hpv[nt][rr].x, hpv[nt][rr].x);
                        float hn1 = fmaf(zv[nt][rr].y, hb1 - hpv[nt][rr].y, hpv[nt][rr].y);
                        *reinterpret_cast<float2*>(&g_h[m * 1024 + n]) = make_float2(hn0, hn1);
                        __half2 hv2 = __floats2half2_rn(hn0, hn1);
                        *reinterpret_cast<__half2*>(&g_sh[m * 1024 + n]) = hv2;
                        size_t ho = (size_t)(m * Tt + t) * Hh + n;
                        *reinterpret_cast<__half2*>(&g_hid[ho]) = hv2;
                    }
                }
            }
        }
        gbarrier(2 * t + 1, G);
    }
}

// ---------------- launch ----------------
extern "C" void kernel_launch(void* const* d_in, const int* in_sizes, int n_in,
                              void* d_out, int out_size)
{
    const int*   x     = (const int*)  d_in[0];
    const float* start = (const float*)d_in[1];
    const float* wte   = (const float*)d_in[2];
    const float* Wr    = (const float*)d_in[3];
    const float* br    = (const float*)d_in[4];
    const float* Wbar  = (const float*)d_in[5];
    const float* bbar  = (const float*)d_in[6];
    const float* Wz    = (const float*)d_in[7];
    const float* bz    = (const float*)d_in[8];
    const float* Whead = (const float*)d_in[9];
    const float* bhead = (const float*)d_in[10];
    float* out = (float*)d_out;

    float* p_pre;
    __nv_bfloat16 *p_ehi, *p_elo, *p_wchi, *p_wclo;
    __half *p_hid, *p_whhi, *p_whlo;
    cudaGetSymbolAddress((void**)&p_pre,  g_pre);
    cudaGetSymbolAddress((void**)&p_ehi,  g_ehi);   cudaGetSymbolAddress((void**)&p_elo,  g_elo);
    cudaGetSymbolAddress((void**)&p_hid,  g_hid);
    cudaGetSymbolAddress((void**)&p_wchi, g_wchi);  cudaGetSymbolAddress((void**)&p_wclo, g_wclo);
    cudaGetSymbolAddress((void**)&p_whhi, g_whhi);  cudaGetSymbolAddress((void**)&p_whlo, g_whlo);

    cudaFuncSetAttribute(k_scan,       cudaFuncAttributeMaxDynamicSharedMemorySize, SC_TOTAL);
    cudaFuncSetAttribute(k_tgemm,      cudaFuncAttributeMaxDynamicSharedMemorySize, SM_TOTAL);
    cudaFuncSetAttribute(k_tgemm_head, cudaFuncAttributeMaxDynamicSharedMemorySize, SMH_TOTAL);

    k_init<<<256, 256>>>(start);
    k_embed<<<(BT * Ee / 4) / 256, 256>>>(x, wte);
    k_cvt_wcat<<<(3 * Hh * Ee) / 256, 256>>>(Wr, Wz, Wbar);
    k_cvt_wH<<<(3 * Hh * Hh) / 256, 256>>>(Wr, Wz, Wbar);
    k_cvt_whead<<<(Vv * Hh) / 256, 256>>>(Whead);

    // pre-projections: 3 gates, N=1024 each, K=512 (bf16-split 3-pass)
    for (int gate = 0; gate < 3; gate++) {
        const float* bias = (gate == 0) ? br : (gate == 1) ? bz : bbar;
        k_tgemm<<<dim3(Hh/128, BT/128), 256, SM_TOTAL>>>(
            p_ehi, p_elo,
            p_wchi + (size_t)gate * Hh * Ee, p_wclo + (size_t)gate * Hh * Ee,
            bias, p_pre + (size_t)gate * BT * Hh, Ee, Hh, Ee/64);
    }

    k_scan<<<128, 256, SC_TOTAL>>>();

    // head: A fp16 single, B fp16 hi/lo, 2-pass
    k_tgemm_head<<<dim3(Vv/128, BT/128), 256, SMH_TOTAL>>>(
        p_hid, p_whhi, p_whlo, bhead, out, Hh, Vv, Hh/64);
}